// round 9
// baseline (speedup 1.0000x reference)
#include <cuda_runtime.h>

// QuantizedLinear(5 -> 10, bits=2) over 4M tokens, fp32.
//
// v1's high-occupancy one-tile-per-block structure, but the 2-bit-dequantized
// weights live in REGISTERS via a thread-pair output split (even lane:
// outputs 0-4, odd lane: 5-9; each pair shares one token). This removes the
// 60 broadcast weight-LDS per token that bound v1 at L1=82%. All global
// traffic stays coalesced float4 via smem staging.

#define THREADS 256
#define TPB 128                 // tokens per block (one thread PAIR per token)
#define IN_F 5
#define OUT_F 10
#define XF (TPB * IN_F)         // 640 floats
#define OF (TPB * OUT_F)        // 1280 floats

__global__ __launch_bounds__(THREADS)
void qlinear2bit_kernel(const float* __restrict__ x,
                        const float* __restrict__ w,
                        const float* __restrict__ bias,
                        float* __restrict__ out,
                        int n_tokens)
{
    __shared__ float sx[XF];    // 2.5 KB
    __shared__ float so[OF];    // 5 KB

    const int t = threadIdx.x;
    const int p = t >> 1;       // token within tile (0..127)
    const int h = t & 1;        // output half: rows h*5 .. h*5+4

    const long long tok0 = (long long)blockIdx.x * TPB;

    // ---- coalesced load of x tile (issue LDG before weight dequant) ----
    const long long xbase = tok0 * IN_F;
    const long long xtotal = (long long)n_tokens * IN_F;
    const bool full = (tok0 + TPB <= (long long)n_tokens);
    if (full) {
        if (t < XF / 4)                                  // 160 float4
            ((float4*)sx)[t] = ((const float4*)(x + xbase))[t];
    } else {
        const int nf = (int)(xtotal - xbase);
        for (int i = t; i < nf; i += THREADS)
            sx[i] = x[xbase + i];
    }

    // ---- dequantize this thread's 5 weight rows into registers ----
    float wd[5][IN_F], b[5];
    #pragma unroll
    for (int j = 0; j < 5; j++) {
        const int o = h * 5 + j;
        float m = 0.0f;
        #pragma unroll
        for (int c = 0; c < IN_F; c++) {
            wd[j][c] = __ldg(&w[o * IN_F + c]);
            m = fmaxf(m, fabsf(wd[j][c]));
        }
        float scale = fmaxf(m, 1e-8f);          // qmax = 2^(bits-1)-1 = 1
        float inv = 1.0f / scale;
        #pragma unroll
        for (int c = 0; c < IN_F; c++) {
            float q = rintf(wd[j][c] * inv);    // round-half-to-even == jnp.round
            wd[j][c] = fminf(fmaxf(q, -2.0f), 1.0f) * scale;
        }
        b[j] = __ldg(&bias[o]);
    }
    __syncthreads();

    // ---- compute: pair shares token p; weights from registers ----
    if (tok0 + p < (long long)n_tokens) {
        float xi[IN_F];
        #pragma unroll
        for (int c = 0; c < IN_F; c++)
            xi[c] = sx[p * IN_F + c];            // pair-broadcast, conflict-free
        #pragma unroll
        for (int j = 0; j < 5; j++) {
            float acc = b[j];
            #pragma unroll
            for (int c = 0; c < IN_F; c++)
                acc = fmaf(xi[c], wd[j][c], acc);
            so[p * OUT_F + h * 5 + j] = acc;     // banks 10p+5h+j: conflict-free
        }
    }
    __syncthreads();

    // ---- coalesced store of out tile ----
    const long long obase = tok0 * OUT_F;
    if (full) {
        float4* og = (float4*)(out + obase);     // 320 float4
        const float4* ss = (const float4*)so;
        og[t] = ss[t];
        if (t < OF / 4 - THREADS)
            og[THREADS + t] = ss[THREADS + t];
    } else {
        const int nof = (int)((long long)n_tokens * OUT_F - obase);
        for (int i = t; i < nof; i += THREADS)
            out[obase + i] = so[i];
    }
}

extern "C" void kernel_launch(void* const* d_in, const int* in_sizes, int n_in,
                              void* d_out, int out_size)
{
    const float* x    = (const float*)d_in[0];   // [N, 5]
    const float* w    = (const float*)d_in[1];   // [10, 5]
    const float* bias = (const float*)d_in[2];   // [10]
    float* out = (float*)d_out;                  // [N, 10]

    const int n_tokens = in_sizes[0] / IN_F;
    const int grid = (n_tokens + TPB - 1) / TPB;
    qlinear2bit_kernel<<<grid, THREADS>>>(x, w, bias, out, n_tokens);
}